// round 12
// baseline (speedup 1.0000x reference)
#include <cuda_runtime.h>
#include <stdint.h>
#include <math_constants.h>

#define NQ   6300
#define NCLS 20
#define CONF_T 0.001f
#define NMS_T  0.5f
#define CAP   512      // per-class mean 315, sd ~17 -> 512 = +11 sigma
#define WPS   17       // mask row stride in words (conflict-free)
#define MROWS (CAP + 1)

__device__ __forceinline__ float sigmoidf_(float x) {
    return 1.0f / (1.0f + expf(-x));
}

// exact-semantics IoU predicate: RN(inter/denom) > 0.5, division avoided
// except inside a tiny boundary window (guard is 100x wider than the rounding
// disagreement region, so result is bit-identical to the divide+compare).
// NaN denom (from NaN pad boxes) -> all compares false -> returns false.
__device__ __forceinline__ bool iou_gt_half(float inter, float denom) {
    if (denom > 0.0f) {
        float half = 0.5f * denom;
        if (inter > half * 1.0000002f) return true;
        if (inter < half * 0.9999998f) return false;
        return (inter / denom) > 0.5f;           // rare boundary: exact
    }
    if (denom == 0.0f) return inter > 0.0f;      // +inf -> true; 0/0=NaN -> false
    return false;                                // negative or NaN denom
}

// ---------------------------------------------------------------------------
// Fused kernel: one block per class. Each block scans all anchors (max-filter
// + argmax), fully decodes its ~315 members, then rank-sorts + mask-builds +
// greedy-scans entirely in shared memory. No device scratch, single launch.
// ---------------------------------------------------------------------------
__global__ void __launch_bounds__(1024, 1)
yolo_nms_fused(const float* __restrict__ conf,
               const float* __restrict__ cls,
               const float* __restrict__ txty,
               const float* __restrict__ grid,
               const float* __restrict__ stridet,
               const float* __restrict__ anch,
               float* __restrict__ out)
{
    __shared__ union {
        struct {                              // phase A (pre-barrier)
            unsigned long long sk[CAP];       // 4 KB unsorted keys
            float4             ubox[CAP];     // 8 KB unsorted boxes
        } a;
        unsigned int mask[MROWS * WPS];       // phase B: ~35 KB suppression bits
    } u;
    __shared__ float4 sbox[CAP];              // 8 KB rank-ordered boxes (+NaN pad)
    __shared__ int    sidx[CAP + 1];          // idx | valid<<16
    __shared__ unsigned char skeepf[CAP];
    __shared__ int scnt;

    const int c    = blockIdx.x;
    const int tid  = threadIdx.x;
    const int nthr = blockDim.x;

    if (tid == 0) scnt = 0;
    __syncthreads();

    // ---- pass 1: max-filter all anchors; argmax + full decode for survivors --
    for (int i = tid; i < NQ; i += nthr) {
        const float4* c4 = (const float4*)(cls + i * NCLS);
        float v[NCLS];
        #pragma unroll
        for (int q = 0; q < 5; q++) {
            float4 t = c4[q];
            v[q * 4 + 0] = t.x; v[q * 4 + 1] = t.y;
            v[q * 4 + 2] = t.z; v[q * 4 + 3] = t.w;
        }

        // cheap exact reject: max via tree (no index tracking)
        float m01 = fmaxf(v[0],  v[1]),  m23 = fmaxf(v[2],  v[3]);
        float m45 = fmaxf(v[4],  v[5]),  m67 = fmaxf(v[6],  v[7]);
        float m89 = fmaxf(v[8],  v[9]),  mab = fmaxf(v[10], v[11]);
        float mcd = fmaxf(v[12], v[13]), mef = fmaxf(v[14], v[15]);
        float mgh = fmaxf(v[16], v[17]), mij = fmaxf(v[18], v[19]);
        float m = fmaxf(fmaxf(fmaxf(m01, m23), fmaxf(m45, m67)),
                        fmaxf(fmaxf(m89, mab), fmaxf(fmaxf(mcd, mef), fmaxf(mgh, mij))));
        if (v[c] < m) continue;               // argmax can't be c (strict-> ties keep earliest)

        // full first-occurrence argmax decides membership exactly (tie cases)
        float mm = v[0]; int am = 0;
        #pragma unroll
        for (int j = 1; j < NCLS; j++)
            if (v[j] > mm) { mm = v[j]; am = j; }
        if (am != c) continue;

        // member: softmax denom + score
        float s = 0.0f;
        #pragma unroll
        for (int j = 0; j < NCLS; j++) s += expf(v[j] - mm);
        float score = sigmoidf_(conf[i]) / s;
        bool valid = (score >= CONF_T);

        // box decode
        int hw = i / 3;
        float4 t = ((const float4*)txty)[i];
        float gx = grid[hw * 2 + 0];
        float gy = grid[hw * 2 + 1];
        float sx = stridet[i * 2 + 0];
        float sy = stridet[i * 2 + 1];
        float aw = anch[i * 2 + 0];
        float ah = anch[i * 2 + 1];

        float cx = (sigmoidf_(t.x) + gx) * sx;
        float cy = (sigmoidf_(t.y) + gy) * sy;
        float bw = expf(t.z) * aw;
        float bh = expf(t.w) * ah;

        float x1 = fminf(1.0f, fmaxf(0.0f, (cx - bw * 0.5f) / 320.0f));
        float y1 = fminf(1.0f, fmaxf(0.0f, (cy - bh * 0.5f) / 320.0f));
        float x2 = fminf(1.0f, fmaxf(0.0f, (cx + bw * 0.5f) / 320.0f));
        float y2 = fminf(1.0f, fmaxf(0.0f, (cy + bh * 0.5f) / 320.0f));

        out[i * 7 + 0] = x1;
        out[i * 7 + 1] = y1;
        out[i * 7 + 2] = x2;
        out[i * 7 + 3] = y2;
        out[i * 7 + 4] = score;
        out[i * 7 + 5] = (float)c;
        // out[i*7+6] written after the scan

        unsigned int ub = __float_as_uint(score);
        unsigned int ma = (ub & 0x80000000u) ? ~ub : (ub | 0x80000000u);
        unsigned int d  = ~ma;                        // descending score, idx asc
        unsigned long long key = ((unsigned long long)d << 32)
                               | ((unsigned long long)(unsigned)i << 1)
                               | (valid ? 1ull : 0ull);

        int p = atomicAdd(&scnt, 1);
        if (p < CAP) {
            u.a.sk[p]   = key;
            u.a.ubox[p] = make_float4(x1, y1, x2, y2);
        }
    }
    __syncthreads();

    const int cnt  = min(scnt, CAP);
    if (cnt == 0) return;
    const int cntp = (cnt + 31) & ~31;       // padded to word multiple (<= CAP)

    // ---- rank sort (keys unique -> permutation); NaN-pad the tail ----
    if (tid < cnt) {
        unsigned long long key = u.a.sk[tid];
        int rank = 0;
        int j = 0;
        for (; j + 8 <= cnt; j += 8) {
            rank += (u.a.sk[j]     < key);
            rank += (u.a.sk[j + 1] < key);
            rank += (u.a.sk[j + 2] < key);
            rank += (u.a.sk[j + 3] < key);
            rank += (u.a.sk[j + 4] < key);
            rank += (u.a.sk[j + 5] < key);
            rank += (u.a.sk[j + 6] < key);
            rank += (u.a.sk[j + 7] < key);
        }
        for (; j < cnt; j++) rank += (u.a.sk[j] < key);

        int idx   = ((unsigned)(key >> 1)) & 0xFFFFu;
        int valid = (int)(key & 1ull);
        sidx[rank] = idx | (valid << 16);
        sbox[rank] = u.a.ubox[tid];
    } else if (tid < cntp) {
        sbox[tid] = make_float4(CUDART_NAN_F, CUDART_NAN_F, CUDART_NAN_F, CUDART_NAN_F);
        sidx[tid] = 0;
    }
    __syncthreads();   // phase A dead; u.mask takes over

    // ---- warp-per-row triangular mask build (diagonal word masked; NaN pad
    // kills j>=cnt; sub-diagonal garbage provably never observed by the scan) --
    const int wpra = cntp >> 5;
    const int wid  = tid >> 5;
    const int lane = tid & 31;
    const int nwrp = nthr >> 5;
    for (int i = wid; i < cnt; i += nwrp) {
        float4 bi  = sbox[i];                      // broadcast
        float  abi = (bi.z - bi.x) * (bi.w - bi.y);
        const int w0 = i >> 5;
        for (int w = w0; w < wpra; w++) {
            int j = (w << 5) + lane;
            float4 q  = sbox[j];
            float  aq = (q.z - q.x) * (q.w - q.y);
            float xx1 = fmaxf(bi.x, q.x);
            float yy1 = fmaxf(bi.y, q.y);
            float xx2 = fminf(bi.z, q.z);
            float yy2 = fminf(bi.w, q.w);
            float inter = fmaxf(1e-28f, xx2 - xx1) * fmaxf(1e-28f, yy2 - yy1);
            bool  pred  = iou_gt_half(inter, abi + aq - inter);
            unsigned word = __ballot_sync(0xFFFFFFFFu, pred);
            if (w == w0) word &= (0xFFFFFFFEu << (i & 31));   // keep j > i only
            if (lane == 0) u.mask[i * WPS + w] = word;
        }
    }
    __syncthreads();

    // ---- serial greedy scan: warp 0, branch-free body ----
    if (tid < 32) {
        const unsigned FULL = 0xFFFFFFFFu;
        unsigned acc = 0, supw = 0;

        unsigned row  = u.mask[tid];               // row 0, lane word
        unsigned rcur = u.mask[0];                 // row 0, word 0 (broadcast)
        int      meta = sidx[0];

        for (int i = 0; i < cnt; i++) {
            const int b = i & 31;
            unsigned bw = __shfl_sync(FULL, acc, i >> 5);   // on-chain only at b==0
            supw = (b == 0) ? bw : supw;

            // unguarded prefetch of i+1 (row cnt exists: MROWS=CAP+1)
            unsigned nrow  = u.mask[(i + 1) * WPS + tid];
            unsigned nrcur = u.mask[(i + 1) * WPS + ((i + 1) >> 5)];
            int      nmeta = sidx[i + 1];

            bool kp = ((meta >> 16) != 0) && !((supw >> b) & 1u);  // uniform
            if (kp) { acc |= row; supw |= rcur; }
            if (tid == 0) skeepf[i] = kp ? 1 : 0;

            row = nrow; rcur = nrcur; meta = nmeta;
        }
    }
    __syncthreads();

    // ---- parallel keep-flag writeback ----
    for (int i = tid; i < cnt; i += nthr)
        out[(sidx[i] & 0xFFFF) * 7 + 6] = skeepf[i] ? 1.0f : 0.0f;
}

// ---------------------------------------------------------------------------
extern "C" void kernel_launch(void* const* d_in, const int* in_sizes, int n_in,
                              void* d_out, int out_size)
{
    const float* conf    = (const float*)d_in[0];
    const float* cls     = (const float*)d_in[1];
    const float* txty    = (const float*)d_in[2];
    const float* grid    = (const float*)d_in[3];
    const float* stridet = (const float*)d_in[4];
    const float* anch    = (const float*)d_in[5];
    float* out = (float*)d_out;

    yolo_nms_fused<<<NCLS, 1024>>>(conf, cls, txty, grid, stridet, anch, out);
}

// round 13
// speedup vs baseline: 1.2695x; 1.2695x over previous
#include <cuda_runtime.h>
#include <stdint.h>
#include <math_constants.h>

#define NQ   6300
#define NCLS 20
#define CONF_T 0.001f
#define NMS_T  0.5f
#define CAP   512      // per-class mean 315, sd ~17 -> 512 = +11 sigma
#define WPS   17       // mask row stride in words (conflict-free)
#define MROWS (CAP + 1)

// Scratch (no allocs allowed). g_cnt zeroed per launch via graph memset node.
__device__ int                g_cnt[NCLS];
__device__ unsigned long long g_ckey[NCLS * CAP];
__device__ float4             g_cbox[NCLS * CAP];

__device__ __forceinline__ float sigmoidf_(float x) {
    return 1.0f / (1.0f + expf(-x));
}

// ---------------------------------------------------------------------------
// K1: decode all anchors; append (key, box) to the owning class's compact list
// ---------------------------------------------------------------------------
__global__ void decode_kernel(const float* __restrict__ conf,
                              const float* __restrict__ cls,
                              const float* __restrict__ txty,
                              const float* __restrict__ grid,
                              const float* __restrict__ stridet,
                              const float* __restrict__ anch,
                              float* __restrict__ out)
{
    int i = blockIdx.x * blockDim.x + threadIdx.x;
    if (i >= NQ) return;

    const float4* c4 = (const float4*)(cls + i * NCLS);
    float v[NCLS];
    #pragma unroll
    for (int q = 0; q < 5; q++) {
        float4 t = c4[q];
        v[q * 4 + 0] = t.x; v[q * 4 + 1] = t.y;
        v[q * 4 + 2] = t.z; v[q * 4 + 3] = t.w;
    }

    float m = v[0]; int am = 0;
    #pragma unroll
    for (int j = 1; j < NCLS; j++)
        if (v[j] > m) { m = v[j]; am = j; }   // first-occurrence argmax

    float s = 0.0f;
    #pragma unroll
    for (int j = 0; j < NCLS; j++) s += expf(v[j] - m);
    float score = sigmoidf_(conf[i]) / s;
    bool valid = (score >= CONF_T);

    int hw = i / 3;
    float4 t = ((const float4*)txty)[i];
    float gx = grid[hw * 2 + 0];
    float gy = grid[hw * 2 + 1];
    float sx = stridet[i * 2 + 0];
    float sy = stridet[i * 2 + 1];
    float aw = anch[i * 2 + 0];
    float ah = anch[i * 2 + 1];

    float cx = (sigmoidf_(t.x) + gx) * sx;
    float cy = (sigmoidf_(t.y) + gy) * sy;
    float bw = expf(t.z) * aw;
    float bh = expf(t.w) * ah;

    float x1 = fminf(1.0f, fmaxf(0.0f, (cx - bw * 0.5f) / 320.0f));
    float y1 = fminf(1.0f, fmaxf(0.0f, (cy - bh * 0.5f) / 320.0f));
    float x2 = fminf(1.0f, fmaxf(0.0f, (cx + bw * 0.5f) / 320.0f));
    float y2 = fminf(1.0f, fmaxf(0.0f, (cy + bh * 0.5f) / 320.0f));

    out[i * 7 + 0] = x1;
    out[i * 7 + 1] = y1;
    out[i * 7 + 2] = x2;
    out[i * 7 + 3] = y2;
    out[i * 7 + 4] = score;
    out[i * 7 + 5] = (float)am;
    // out[i*7+6] (keep) written by nms_kernel

    unsigned int u  = __float_as_uint(score);
    unsigned int ma = (u & 0x80000000u) ? ~u : (u | 0x80000000u);
    unsigned int d  = ~ma;                       // descending score, idx asc
    unsigned long long key = ((unsigned long long)d << 32)
                           | ((unsigned long long)(unsigned)i << 1)
                           | (valid ? 1ull : 0ull);

    int p = atomicAdd(&g_cnt[am], 1);            // append order irrelevant (canonical key)
    if (p < CAP) {
        g_ckey[am * CAP + p] = key;
        g_cbox[am * CAP + p] = make_float4(x1, y1, x2, y2);
    }
}

// exact-semantics IoU predicate: RN(inter/denom) > 0.5, division avoided
// except inside a tiny boundary window (guard is 100x wider than the rounding
// disagreement region, so result is bit-identical to the divide+compare).
// NaN denom (from NaN pad boxes) -> all compares false -> returns false.
__device__ __forceinline__ bool iou_gt_half(float inter, float denom) {
    if (denom > 0.0f) {
        float half = 0.5f * denom;
        if (inter > half * 1.0000002f) return true;
        if (inter < half * 0.9999998f) return false;
        return (inter / denom) > 0.5f;           // rare boundary: exact
    }
    if (denom == 0.0f) return inter > 0.0f;      // +inf -> true; 0/0=NaN -> false
    return false;                                // negative or NaN denom
}

// ---------------------------------------------------------------------------
// K2: compact-list load + warp-per-i rank sort + ballot mask build + bit-scan
// ---------------------------------------------------------------------------
__global__ void __launch_bounds__(1024, 1)
nms_kernel(float* __restrict__ out)
{
    __shared__ union {
        struct {                              // phase A
            unsigned long long sk[CAP];       // 4 KB unsorted keys
            float4             ubox[CAP];     // 8 KB unsorted boxes
        } a;
        unsigned int mask[MROWS * WPS];       // phase B: ~35 KB suppression bits
    } u;
    __shared__ float4 sbox[CAP];              // 8 KB rank-ordered boxes (+NaN pad)
    __shared__ int    sidx[CAP + 1];
    __shared__ unsigned char skeepf[CAP];

    const int c    = blockIdx.x;
    const int tid  = threadIdx.x;
    const int nthr = blockDim.x;

    const int cnt  = min(g_cnt[c], CAP);
    if (cnt == 0) return;
    const int cntp = (cnt + 31) & ~31;

    // coalesced load of this class's compact list
    if (tid < cnt) {
        u.a.sk[tid]   = g_ckey[c * CAP + tid];
        u.a.ubox[tid] = g_cbox[c * CAP + tid];
    }
    if (tid >= cnt && tid < cntp) {           // NaN pad (into final arrays)
        sbox[tid] = make_float4(CUDART_NAN_F, CUDART_NAN_F, CUDART_NAN_F, CUDART_NAN_F);
        sidx[tid] = 0;
    }
    __syncthreads();

    // warp-per-i rank sort: keys unique -> rank is a permutation
    {
        const int wid  = tid >> 5;
        const int lane = tid & 31;
        for (int i = wid; i < cnt; i += (nthr >> 5)) {
            unsigned long long key = u.a.sk[i];
            int part = 0;
            for (int j = lane; j < cnt; j += 32)
                part += (u.a.sk[j] < key);
            int rank = __reduce_add_sync(0xFFFFFFFFu, part);
            if (lane == 0) {
                int idx   = ((unsigned)(key >> 1)) & 0xFFFFu;
                int valid = (int)(key & 1ull);
                sidx[rank] = idx | (valid << 16);
                sbox[rank] = u.a.ubox[i];
            }
        }
    }
    __syncthreads();   // phase A dead; u.mask takes over

    // warp-per-row triangular mask build (diagonal word masked; NaN pad kills
    // j>=cnt; sub-diagonal garbage never observed by the scan)
    const int wpra = cntp >> 5;
    const int wid  = tid >> 5;
    const int lane = tid & 31;
    const int nwrp = nthr >> 5;
    for (int i = wid; i < cnt; i += nwrp) {
        float4 bi  = sbox[i];                      // broadcast
        float  abi = (bi.z - bi.x) * (bi.w - bi.y);
        const int w0 = i >> 5;
        for (int w = w0; w < wpra; w++) {
            int j = (w << 5) + lane;
            float4 q  = sbox[j];
            float  aq = (q.z - q.x) * (q.w - q.y);
            float xx1 = fmaxf(bi.x, q.x);
            float yy1 = fmaxf(bi.y, q.y);
            float xx2 = fminf(bi.z, q.z);
            float yy2 = fminf(bi.w, q.w);
            float inter = fmaxf(1e-28f, xx2 - xx1) * fmaxf(1e-28f, yy2 - yy1);
            bool  pred  = iou_gt_half(inter, abi + aq - inter);
            unsigned word = __ballot_sync(0xFFFFFFFFu, pred);
            if (w == w0) word &= (0xFFFFFFFEu << (i & 31));   // keep j > i only
            if (lane == 0) u.mask[i * WPS + w] = word;
        }
    }
    __syncthreads();

    // serial greedy scan: warp 0, branch-free body
    if (tid < 32) {
        const unsigned FULL = 0xFFFFFFFFu;
        unsigned acc = 0, supw = 0;

        unsigned row  = u.mask[tid];               // row 0, lane word
        unsigned rcur = u.mask[0];                 // row 0, word 0 (broadcast)
        int      meta = sidx[0];

        for (int i = 0; i < cnt; i++) {
            const int b = i & 31;
            unsigned bw = __shfl_sync(FULL, acc, i >> 5);   // on-chain only at b==0
            supw = (b == 0) ? bw : supw;

            // unguarded prefetch of i+1 (row cnt exists: MROWS=CAP+1)
            unsigned nrow  = u.mask[(i + 1) * WPS + tid];
            unsigned nrcur = u.mask[(i + 1) * WPS + ((i + 1) >> 5)];
            int      nmeta = sidx[i + 1];

            bool kp = ((meta >> 16) != 0) && !((supw >> b) & 1u);  // uniform
            if (kp) { acc |= row; supw |= rcur; }
            if (tid == 0) skeepf[i] = kp ? 1 : 0;

            row = nrow; rcur = nrcur; meta = nmeta;
        }
    }
    __syncthreads();

    // parallel keep-flag writeback
    for (int i = tid; i < cnt; i += nthr)
        out[(sidx[i] & 0xFFFF) * 7 + 6] = skeepf[i] ? 1.0f : 0.0f;
}

// ---------------------------------------------------------------------------
extern "C" void kernel_launch(void* const* d_in, const int* in_sizes, int n_in,
                              void* d_out, int out_size)
{
    const float* conf    = (const float*)d_in[0];
    const float* cls     = (const float*)d_in[1];
    const float* txty    = (const float*)d_in[2];
    const float* grid    = (const float*)d_in[3];
    const float* stridet = (const float*)d_in[4];
    const float* anch    = (const float*)d_in[5];
    float* out = (float*)d_out;

    void* cnt_ptr = nullptr;
    cudaGetSymbolAddress(&cnt_ptr, g_cnt);                 // address query, capture-safe
    cudaMemsetAsync(cnt_ptr, 0, NCLS * sizeof(int));       // graph memset node

    decode_kernel<<<(NQ + 255) / 256, 256>>>(conf, cls, txty, grid, stridet, anch, out);
    nms_kernel<<<NCLS, 1024>>>(out);
}

// round 14
// speedup vs baseline: 1.5823x; 1.2463x over previous
#include <cuda_runtime.h>
#include <stdint.h>
#include <math_constants.h>

#define NQ   6300
#define NCLS 20
#define CONF_T 0.001f
#define NMS_T  0.5f
#define CAP   512      // per-class mean 315, sd ~17 -> 512 = +11 sigma
#define WPS   17       // mask row stride in words (conflict-free)
#define MROWS (CAP + 1)

// Scratch (no allocs). g_cnt starts zeroed (static init); nms re-zeros it
// at the end of every launch so each graph replay sees the same precondition.
__device__ int                g_cnt[NCLS];
__device__ unsigned long long g_ckey[NCLS * CAP];
__device__ float4             g_cbox[NCLS * CAP];

__device__ __forceinline__ float sigmoidf_(float x) {
    return 1.0f / (1.0f + expf(-x));
}

// ---------------------------------------------------------------------------
// K1: decode all anchors; append (key, box) to the owning class's compact list
// ---------------------------------------------------------------------------
__global__ void decode_kernel(const float* __restrict__ conf,
                              const float* __restrict__ cls,
                              const float* __restrict__ txty,
                              const float* __restrict__ grid,
                              const float* __restrict__ stridet,
                              const float* __restrict__ anch,
                              float* __restrict__ out)
{
    int i = blockIdx.x * blockDim.x + threadIdx.x;
    if (i >= NQ) return;

    const float4* c4 = (const float4*)(cls + i * NCLS);
    float v[NCLS];
    #pragma unroll
    for (int q = 0; q < 5; q++) {
        float4 t = c4[q];
        v[q * 4 + 0] = t.x; v[q * 4 + 1] = t.y;
        v[q * 4 + 2] = t.z; v[q * 4 + 3] = t.w;
    }

    float m = v[0]; int am = 0;
    #pragma unroll
    for (int j = 1; j < NCLS; j++)
        if (v[j] > m) { m = v[j]; am = j; }   // first-occurrence argmax

    float s = 0.0f;
    #pragma unroll
    for (int j = 0; j < NCLS; j++) s += expf(v[j] - m);
    float score = sigmoidf_(conf[i]) / s;
    bool valid = (score >= CONF_T);

    int hw = i / 3;
    float4 t = ((const float4*)txty)[i];
    float gx = grid[hw * 2 + 0];
    float gy = grid[hw * 2 + 1];
    float sx = stridet[i * 2 + 0];
    float sy = stridet[i * 2 + 1];
    float aw = anch[i * 2 + 0];
    float ah = anch[i * 2 + 1];

    float cx = (sigmoidf_(t.x) + gx) * sx;
    float cy = (sigmoidf_(t.y) + gy) * sy;
    float bw = expf(t.z) * aw;
    float bh = expf(t.w) * ah;

    float x1 = fminf(1.0f, fmaxf(0.0f, (cx - bw * 0.5f) / 320.0f));
    float y1 = fminf(1.0f, fmaxf(0.0f, (cy - bh * 0.5f) / 320.0f));
    float x2 = fminf(1.0f, fmaxf(0.0f, (cx + bw * 0.5f) / 320.0f));
    float y2 = fminf(1.0f, fmaxf(0.0f, (cy + bh * 0.5f) / 320.0f));

    out[i * 7 + 0] = x1;
    out[i * 7 + 1] = y1;
    out[i * 7 + 2] = x2;
    out[i * 7 + 3] = y2;
    out[i * 7 + 4] = score;
    out[i * 7 + 5] = (float)am;
    // out[i*7+6] (keep) written by nms_kernel

    unsigned int u  = __float_as_uint(score);
    unsigned int ma = (u & 0x80000000u) ? ~u : (u | 0x80000000u);
    unsigned int d  = ~ma;                       // descending score, idx asc
    unsigned long long key = ((unsigned long long)d << 32)
                           | ((unsigned long long)(unsigned)i << 1)
                           | (valid ? 1ull : 0ull);

    int p = atomicAdd(&g_cnt[am], 1);            // append order irrelevant (canonical key)
    if (p < CAP) {
        g_ckey[am * CAP + p] = key;
        g_cbox[am * CAP + p] = make_float4(x1, y1, x2, y2);
    }
}

// exact-semantics IoU predicate: RN(inter/denom) > 0.5, division avoided
// except inside a tiny boundary window (guard is 100x wider than the rounding
// disagreement region, so result is bit-identical to the divide+compare).
// NaN denom (from NaN pad boxes) -> all compares false -> returns false.
__device__ __forceinline__ bool iou_gt_half(float inter, float denom) {
    if (denom > 0.0f) {
        float half = 0.5f * denom;
        if (inter > half * 1.0000002f) return true;
        if (inter < half * 0.9999998f) return false;
        return (inter / denom) > 0.5f;           // rare boundary: exact
    }
    if (denom == 0.0f) return inter > 0.0f;      // +inf -> true; 0/0=NaN -> false
    return false;                                // negative or NaN denom
}

// ---------------------------------------------------------------------------
// K2: compact-list load + warp rank sort + ballot mask build + word-blocked scan
// ---------------------------------------------------------------------------
__global__ void __launch_bounds__(1024, 1)
nms_kernel(float* __restrict__ out)
{
    __shared__ union {
        struct {                              // phase A
            unsigned long long sk[CAP];       // 4 KB unsorted keys
            float4             ubox[CAP];     // 8 KB unsorted boxes
        } a;
        unsigned int mask[MROWS * WPS];       // phase B: ~35 KB suppression bits
    } u;
    __shared__ float4 sbox[CAP];              // 8 KB rank-ordered boxes (+NaN pad)
    __shared__ int    sidx[CAP + 1];
    __shared__ unsigned int skeepw[CAP / 32]; // packed keep bits per word

    const int c    = blockIdx.x;
    const int tid  = threadIdx.x;
    const int nthr = blockDim.x;

    const int cnt  = min(g_cnt[c], CAP);
    if (cnt == 0) return;                      // g_cnt[c] already 0, no reset needed
    const int cntp = (cnt + 31) & ~31;

    // coalesced load of this class's compact list
    if (tid < cnt) {
        u.a.sk[tid]   = g_ckey[c * CAP + tid];
        u.a.ubox[tid] = g_cbox[c * CAP + tid];
    }
    if (tid >= cnt && tid < cntp) {           // NaN pad (into final arrays)
        sbox[tid] = make_float4(CUDART_NAN_F, CUDART_NAN_F, CUDART_NAN_F, CUDART_NAN_F);
        sidx[tid] = 0;
    }
    __syncthreads();

    // warp-per-i rank sort: keys unique -> rank is a permutation
    {
        const int wid  = tid >> 5;
        const int lane = tid & 31;
        for (int i = wid; i < cnt; i += (nthr >> 5)) {
            unsigned long long key = u.a.sk[i];
            int part = 0;
            for (int j = lane; j < cnt; j += 32)
                part += (u.a.sk[j] < key);
            int rank = __reduce_add_sync(0xFFFFFFFFu, part);
            if (lane == 0) {
                int idx   = ((unsigned)(key >> 1)) & 0xFFFFu;
                int valid = (int)(key & 1ull);
                sidx[rank] = idx | (valid << 16);
                sbox[rank] = u.a.ubox[i];
            }
        }
    }
    __syncthreads();   // phase A dead; u.mask takes over

    // warp-per-row triangular mask build (diagonal word masked; NaN pad kills
    // j>=cnt; sub-diagonal garbage never observed by the scan)
    const int wpra = cntp >> 5;
    const int wid  = tid >> 5;
    const int lane = tid & 31;
    const int nwrp = nthr >> 5;
    for (int i = wid; i < cnt; i += nwrp) {
        float4 bi  = sbox[i];                      // broadcast
        float  abi = (bi.z - bi.x) * (bi.w - bi.y);
        const int w0 = i >> 5;
        for (int w = w0; w < wpra; w++) {
            int j = (w << 5) + lane;
            float4 q  = sbox[j];
            float  aq = (q.z - q.x) * (q.w - q.y);
            float xx1 = fmaxf(bi.x, q.x);
            float yy1 = fmaxf(bi.y, q.y);
            float xx2 = fminf(bi.z, q.z);
            float yy2 = fminf(bi.w, q.w);
            float inter = fmaxf(1e-28f, xx2 - xx1) * fmaxf(1e-28f, yy2 - yy1);
            bool  pred  = iou_gt_half(inter, abi + aq - inter);
            unsigned word = __ballot_sync(0xFFFFFFFFu, pred);
            if (w == w0) word &= (0xFFFFFFFEu << (i & 31));   // keep j > i only
            if (lane == 0) u.mask[i * WPS + w] = word;
        }
    }
    __syncthreads();

    // serial greedy scan: warp 0, word-blocked. One shfl per 32 candidates;
    // inner loop is LDS + bit algebra only (chain: supw |= rcur, ~5 cyc).
    // acc lane w carries cross-word suppression into word w's shfl; rows in
    // [cnt, cntp) have valid=0 (sidx pad) so their garbage mask rows are inert.
    if (tid < 32) {
        const unsigned FULL = 0xFFFFFFFFu;
        unsigned acc = 0;
        const int nw = cntp >> 5;
        for (int w = 0; w < nw; w++) {
            unsigned supw  = __shfl_sync(FULL, acc, w);
            unsigned keepw = 0;
            const int base = w << 5;
            #pragma unroll
            for (int b = 0; b < 32; b++) {
                const int i = base + b;
                unsigned row_lane = u.mask[i * WPS + tid];  // lane's word of row i
                unsigned rcur     = u.mask[i * WPS + w];    // broadcast: row i word w
                int      meta     = sidx[i];
                bool kp = ((meta >> 16) != 0) && !((supw >> b) & 1u);   // uniform
                if (kp) { acc |= row_lane; supw |= rcur; keepw |= (1u << b); }
            }
            if (tid == 0) skeepw[w] = keepw;
        }
    }
    __syncthreads();

    // parallel keep-flag writeback + counter reset for next replay
    for (int i = tid; i < cnt; i += nthr)
        out[(sidx[i] & 0xFFFF) * 7 + 6] = (skeepw[i >> 5] >> (i & 31)) & 1u ? 1.0f : 0.0f;
    if (tid == 0) g_cnt[c] = 0;
}

// ---------------------------------------------------------------------------
extern "C" void kernel_launch(void* const* d_in, const int* in_sizes, int n_in,
                              void* d_out, int out_size)
{
    const float* conf    = (const float*)d_in[0];
    const float* cls     = (const float*)d_in[1];
    const float* txty    = (const float*)d_in[2];
    const float* grid    = (const float*)d_in[3];
    const float* stridet = (const float*)d_in[4];
    const float* anch    = (const float*)d_in[5];
    float* out = (float*)d_out;

    decode_kernel<<<(NQ + 255) / 256, 256>>>(conf, cls, txty, grid, stridet, anch, out);
    nms_kernel<<<NCLS, 1024>>>(out);
}